// round 2
// baseline (speedup 1.0000x reference)
#include <cuda_runtime.h>
#include <cstdint>

#define NDIM   128    // node/out dim
#define EDIM   64
#define KDIM   192    // NDIM + EDIM
#define BM     128    // edges per CTA tile
#define THREADS 256

// padded smem strides (floats) — chosen for conflict-free fragment loads
#define AS_STRIDE 196   // (4r + c) % 32 bijective over (g,t)
#define WS_STRIDE 136   // (8r + c) % 32 bijective over (t,g)

#define SMEM_FLOATS (KDIM * WS_STRIDE + BM * AS_STRIDE + NDIM)
#define SMEM_BYTES  (SMEM_FLOATS * sizeof(float))

// Flag: 1 if src_idx buffer is int64, 0 if int32. Set by detect_kernel.
__device__ int g_idx_is64;

__global__ void detect_idx_dtype_kernel(const int* __restrict__ buf, int n_words) {
    // int64 little-endian of small non-negative values => every odd 32-bit word is 0.
    int nz = 0;
    for (int i = 1; i < n_words; i += 2) nz += (buf[i] != 0);
    g_idx_is64 = (nz == 0) ? 1 : 0;
}

__device__ __forceinline__ uint32_t f32_to_tf32(float x) {
    uint32_t r;
    asm volatile("cvt.rna.tf32.f32 %0, %1;" : "=r"(r) : "f"(x));
    return r;
}

__device__ __forceinline__ void mma_tf32(float d[4], const uint32_t a[4], const uint32_t b[2]) {
    asm volatile(
        "mma.sync.aligned.m16n8k8.row.col.f32.tf32.tf32.f32 "
        "{%0,%1,%2,%3}, {%4,%5,%6,%7}, {%8,%9}, {%0,%1,%2,%3};\n"
        : "+f"(d[0]), "+f"(d[1]), "+f"(d[2]), "+f"(d[3])
        : "r"(a[0]), "r"(a[1]), "r"(a[2]), "r"(a[3]),
          "r"(b[0]), "r"(b[1]));
}

__global__ void __launch_bounds__(THREADS, 1)
atom2bond_kernel(const float* __restrict__ atom,
                 const float* __restrict__ edge,
                 const void* __restrict__ src_idx,
                 const float* __restrict__ Wg,
                 const float* __restrict__ bg,
                 float* __restrict__ out,
                 int E, int ntiles, long n_nodes) {
    extern __shared__ float smem[];
    float* Ws = smem;                         // [KDIM][WS_STRIDE] tf32 bits
    float* As = Ws + KDIM * WS_STRIDE;        // [BM][AS_STRIDE]   tf32 bits
    float* Bs = As + BM * AS_STRIDE;          // [NDIM] bias (fp32)

    const int tid  = threadIdx.x;
    const int lane = tid & 31;
    const int warp = tid >> 5;
    const int g = lane >> 2;      // groupID
    const int t = lane & 3;       // threadID_in_group
    const int wm = warp >> 1;     // 0..3 : edge-row block (32 edges each)
    const int wn = warp & 1;      // 0..1 : output-col half (64 cols each)

    const int is64 = g_idx_is64;

    // ---- Load W once per CTA (tf32-converted), and bias ----
    {
        const int F4 = NDIM / 4;  // 32 float4 per W row
        for (int v = tid; v < KDIM * F4; v += THREADS) {
            int row = v / F4;
            int c4  = (v % F4) * 4;
            float4 w = *(const float4*)(Wg + (long)row * NDIM + c4);
            float* dst = Ws + row * WS_STRIDE + c4;
            dst[0] = __uint_as_float(f32_to_tf32(w.x));
            dst[1] = __uint_as_float(f32_to_tf32(w.y));
            dst[2] = __uint_as_float(f32_to_tf32(w.z));
            dst[3] = __uint_as_float(f32_to_tf32(w.w));
        }
        if (tid < NDIM) Bs[tid] = bg[tid];
    }

    // ---- Persistent loop over edge tiles ----
    for (int tile = blockIdx.x; tile < ntiles; tile += gridDim.x) {
        const long eb = (long)tile * BM;

        __syncthreads();  // previous compute done before overwriting As

        // Gather + concat A tile into smem (tf32-converted).
        // 2 threads per row; each handles 24 float4 (row = 48 float4 = 192 f)
        {
            const int r    = tid >> 1;
            const int half = tid & 1;
            const long e   = eb + r;
            const bool valid = (e < E);
            long s = 0;
            if (valid) {
                s = is64 ? (long)((const long long*)src_idx)[e]
                         : (long)((const int*)src_idx)[e];
                // defense-in-depth: never index out of the atom table
                if (s < 0) s = 0;
                if (s >= n_nodes) s = n_nodes - 1;
            }
            const float* arow = atom + s * (long)NDIM;
            const float* erow = edge + e * (long)EDIM;
            float* dst = As + r * AS_STRIDE;
            #pragma unroll
            for (int q = 0; q < 24; q++) {
                int c4 = (half * 24 + q) * 4;
                float4 val;
                if (!valid)            val = make_float4(0.f, 0.f, 0.f, 0.f);
                else if (c4 < NDIM)    val = *(const float4*)(arow + c4);
                else                   val = *(const float4*)(erow + (c4 - NDIM));
                dst[c4 + 0] = __uint_as_float(f32_to_tf32(val.x));
                dst[c4 + 1] = __uint_as_float(f32_to_tf32(val.y));
                dst[c4 + 2] = __uint_as_float(f32_to_tf32(val.z));
                dst[c4 + 3] = __uint_as_float(f32_to_tf32(val.w));
            }
        }
        __syncthreads();

        // ---- Main MMA loop: warp computes 32 edges x 64 outputs ----
        float acc[2][8][4];
        #pragma unroll
        for (int i = 0; i < 2; i++)
            #pragma unroll
            for (int j = 0; j < 8; j++)
                #pragma unroll
                for (int c = 0; c < 4; c++) acc[i][j][c] = 0.f;

        #pragma unroll
        for (int kk = 0; kk < KDIM / 8; kk++) {
            const int k0 = kk * 8;
            uint32_t a[2][4];
            #pragma unroll
            for (int i = 0; i < 2; i++) {
                const float* Ar = As + (wm * 32 + i * 16 + g) * AS_STRIDE + k0 + t;
                a[i][0] = __float_as_uint(Ar[0]);
                a[i][1] = __float_as_uint(Ar[8 * AS_STRIDE]);
                a[i][2] = __float_as_uint(Ar[4]);
                a[i][3] = __float_as_uint(Ar[8 * AS_STRIDE + 4]);
            }
            uint32_t b[8][2];
            #pragma unroll
            for (int j = 0; j < 8; j++) {
                const float* Wr = Ws + (k0 + t) * WS_STRIDE + wn * 64 + j * 8 + g;
                b[j][0] = __float_as_uint(Wr[0]);
                b[j][1] = __float_as_uint(Wr[4 * WS_STRIDE]);
            }
            #pragma unroll
            for (int i = 0; i < 2; i++)
                #pragma unroll
                for (int j = 0; j < 8; j++)
                    mma_tf32(acc[i][j], a[i], b[j]);
        }

        // ---- Epilogue: bias + relu, float2 stores ----
        #pragma unroll
        for (int i = 0; i < 2; i++) {
            const long e0 = eb + wm * 32 + i * 16 + g;
            #pragma unroll
            for (int rr = 0; rr < 2; rr++) {
                const long e = e0 + rr * 8;
                if (e < E) {
                    float* orow = out + e * (long)NDIM;
                    #pragma unroll
                    for (int j = 0; j < 8; j++) {
                        const int c = wn * 64 + j * 8 + 2 * t;
                        float v0 = fmaxf(acc[i][j][rr * 2 + 0] + Bs[c], 0.f);
                        float v1 = fmaxf(acc[i][j][rr * 2 + 1] + Bs[c + 1], 0.f);
                        *(float2*)(orow + c) = make_float2(v0, v1);
                    }
                }
            }
        }
    }
}

extern "C" void kernel_launch(void* const* d_in, const int* in_sizes, int n_in,
                              void* d_out, int out_size) {
    const float* atom = (const float*)d_in[0];      // [N_NODES, 128] f32
    const float* edge = (const float*)d_in[1];      // [E, 64] f32
    const void*  src  = d_in[2];                    // [E] int32 OR int64 (detected)
    const float* W    = (const float*)d_in[3];      // [192, 128] f32
    const float* b    = (const float*)d_in[4];      // [128] f32
    float* out = (float*)d_out;                     // [E, 128] f32

    const int  E       = in_sizes[2];
    const long n_nodes = (long)in_sizes[0] / NDIM;
    const int  ntiles  = (E + BM - 1) / BM;

    // Detect index dtype: safe to read E int32 words under either dtype.
    int n_words = E < 2048 ? E : 2048;
    detect_idx_dtype_kernel<<<1, 1>>>((const int*)src, n_words);

    cudaFuncSetAttribute(atom2bond_kernel,
                         cudaFuncAttributeMaxDynamicSharedMemorySize, SMEM_BYTES);

    int grid = ntiles < 148 ? ntiles : 148;
    atom2bond_kernel<<<grid, THREADS, SMEM_BYTES>>>(atom, edge, src, W, b, out,
                                                    E, ntiles, n_nodes);
}